// round 3
// baseline (speedup 1.0000x reference)
#include <cuda_runtime.h>
#include <cstdint>
#include <cstddef>

// ============================================================================
// Problem dims
// ============================================================================
constexpr int NBR = 36;    // branches (IN_DIM)
constexpr int HID = 512;
constexpr int EMB = 1024;
constexpr int NSEG = HID + 1;  // 513 segments
constexpr int BATCH = 2048;

// ============================================================================
// Scratch (__device__ globals — allowed; no runtime allocation)
// ============================================================================
__device__ float g_tsort[NBR * HID];   // sorted knees per branch
__device__ int   g_sidx [NBR * HID];   // original unit index in sorted order
__device__ float g_dss  [NBR * HID];   // slope delta, sorted order
__device__ float g_dcs  [NBR * HID];   // intercept delta, sorted order
__device__ float g_slo  [NBR * HID];   // base slope per unit (unsorted, j order)
__device__ float g_clo  [NBR * HID];   // base intercept per unit (unsorted)

// Fused table: per (branch, rank) one row of 2*EMB floats: [SL(0..1023) | SC(0..1023)]
__device__ float g_T[(size_t)NBR * NSEG * 2 * EMB];  // 151 MB

// ============================================================================
// Kernel 1: per-branch knee computation + bitonic sort (36 blocks x 512 thr)
//
// leaky(z) = z (z>=0) else 0.01 z,  z = W1*x + b1;  knee t = -b1/W1.
//  W1>0: x<t -> (0.01W1, 0.01b1); x>=t -> (W1, b1)      => ds=+0.99W1, dc=+0.99b1
//  W1<0: x<t -> (W1, b1);         x>=t -> (0.01W1,0.01b1) => ds=-0.99W1, dc=-0.99b1
//  W1=0: constant leaky(b1); t=+inf, ds=dc=0
// (Value is continuous at the knee, so rank ties are harmless.)
// ============================================================================
__global__ void __launch_bounds__(HID)
prep_kernel(const float* __restrict__ W1, const float* __restrict__ b1) {
    __shared__ float sk[HID];
    __shared__ int   sv[HID];
    __shared__ float sds[HID];
    __shared__ float sdc[HID];

    const int i = blockIdx.x;
    const int j = threadIdx.x;

    const float w = W1[i * HID + j];
    const float b = b1[i * HID + j];

    float t, slo, clo, ds, dc;
    if (w > 0.0f) {
        t = -b / w;
        slo = 0.01f * w; clo = 0.01f * b;
        ds = 0.99f * w;  dc = 0.99f * b;
    } else if (w < 0.0f) {
        t = -b / w;
        slo = w; clo = b;
        ds = -0.99f * w; dc = -0.99f * b;
    } else {
        t = __int_as_float(0x7f800000);  // +inf (never crossed)
        slo = 0.0f;
        clo = (b >= 0.0f) ? b : 0.01f * b;
        ds = 0.0f; dc = 0.0f;
    }

    g_slo[i * HID + j] = slo;
    g_clo[i * HID + j] = clo;

    sk[j] = t; sv[j] = j; sds[j] = ds; sdc[j] = dc;
    __syncthreads();

    // Bitonic sort ascending on sk, carrying sv
    for (int k = 2; k <= HID; k <<= 1) {
        for (int jj = k >> 1; jj > 0; jj >>= 1) {
            int ixj = j ^ jj;
            if (ixj > j) {
                bool up = ((j & k) == 0);
                float a = sk[j], c = sk[ixj];
                bool sw = up ? (a > c) : (a < c);
                if (sw) {
                    sk[j] = c; sk[ixj] = a;
                    int tv = sv[j]; sv[j] = sv[ixj]; sv[ixj] = tv;
                }
            }
            __syncthreads();
        }
    }

    const int src = sv[j];
    g_tsort[i * HID + j] = sk[j];
    g_sidx [i * HID + j] = src;
    g_dss  [i * HID + j] = sds[src];
    g_dcs  [i * HID + j] = sdc[src];
}

// ============================================================================
// Kernel 2: build prefix tables. grid (EMB/DCH, NBR), DCH threads.
//   SL[i,0,d] = sum_j slo_j W2[i,j,d];   SC[i,0,d] = sum_j clo_j W2[i,j,d] + b2
//   SL[i,r,d] = SL[i,r-1,d] + ds_sorted[r-1] * W2[i, sidx[r-1], d]   (same for SC)
// Pass 2 re-reads the W2 slice pass 1 just touched -> L2 hits (73 MB resident).
// ============================================================================
constexpr int DCH = 128;

__global__ void __launch_bounds__(DCH)
build_kernel(const float* __restrict__ W2, const float* __restrict__ b2) {
    __shared__ float s_slo[HID];
    __shared__ float s_clo[HID];
    __shared__ float s_ds [HID];
    __shared__ float s_dc [HID];
    __shared__ int   s_ix [HID];

    const int i = blockIdx.y;
    const int d = blockIdx.x * DCH + threadIdx.x;
    const int tid = threadIdx.x;

    for (int r = tid; r < HID; r += DCH) {
        s_slo[r] = g_slo[i * HID + r];
        s_clo[r] = g_clo[i * HID + r];
        s_ds [r] = g_dss[i * HID + r];
        s_dc [r] = g_dcs[i * HID + r];
        s_ix [r] = g_sidx[i * HID + r];
    }
    __syncthreads();

    const float* w2b = W2 + (size_t)i * HID * EMB + d;

    // Base pass (natural j order)
    float sl = 0.0f;
    float sc = b2[i * EMB + d];
#pragma unroll 4
    for (int j = 0; j < HID; j++) {
        float w2 = w2b[(size_t)j * EMB];
        sl = fmaf(s_slo[j], w2, sl);
        sc = fmaf(s_clo[j], w2, sc);
    }

    float* trow = g_T + ((size_t)i * NSEG) * (2 * EMB) + d;
    trow[0]   = sl;
    trow[EMB] = sc;

    // Prefix pass (sorted knee order)
#pragma unroll 4
    for (int r = 1; r <= HID; r++) {
        float w2 = w2b[(size_t)s_ix[r - 1] * EMB];
        sl = fmaf(s_ds[r - 1], w2, sl);
        sc = fmaf(s_dc[r - 1], w2, sc);
        trow[(size_t)r * (2 * EMB)]       = sl;
        trow[(size_t)r * (2 * EMB) + EMB] = sc;
    }
}

// ============================================================================
// Kernel 3: apply. grid (BATCH/BCH, NBR), 256 threads.
//   out[b,i,d] = x[b,i] * SL[i, r(x), d] + SC[i, r(x), d]
// blockIdx.x fastest -> all 64 blocks of one branch run ~together, sharing the
// branch's 4.2 MB table slice in L2.
// ============================================================================
constexpr int BCH = 32;
constexpr int ATHREADS = 256;  // 256 * float4 = 1024 d

__global__ void __launch_bounds__(ATHREADS)
apply_kernel(const float* __restrict__ x, float* __restrict__ out) {
    __shared__ float s_t[HID];
    __shared__ float s_x[BCH];
    __shared__ int   s_r[BCH];

    const int i = blockIdx.y;
    const int b0 = blockIdx.x * BCH;
    const int tid = threadIdx.x;

    for (int r = tid; r < HID; r += ATHREADS)
        s_t[r] = g_tsort[i * HID + r];
    __syncthreads();

    if (tid < BCH) {
        const float xv = x[(size_t)(b0 + tid) * NBR + i];
        // r = count of knees <= xv (binary search, 9 steps)
        int lo = 0, hi = HID;
        while (lo < hi) {
            int mid = (lo + hi) >> 1;
            if (s_t[mid] <= xv) lo = mid + 1; else hi = mid;
        }
        s_x[tid] = xv;
        s_r[tid] = lo;
    }
    __syncthreads();

    const int d4 = tid * 4;
#pragma unroll 2
    for (int bb = 0; bb < BCH; bb++) {
        const int r = s_r[bb];
        const float xv = s_x[bb];
        const float* trow = g_T + ((size_t)i * NSEG + r) * (2 * EMB);
        float4 sl = *(const float4*)(trow + d4);
        float4 sc = *(const float4*)(trow + EMB + d4);
        float4 v;
        v.x = fmaf(xv, sl.x, sc.x);
        v.y = fmaf(xv, sl.y, sc.y);
        v.z = fmaf(xv, sl.z, sc.z);
        v.w = fmaf(xv, sl.w, sc.w);
        *(float4*)(out + ((size_t)(b0 + bb) * NBR + i) * EMB + d4) = v;
    }
}

// ============================================================================
// Launch
// ============================================================================
extern "C" void kernel_launch(void* const* d_in, const int* in_sizes, int n_in,
                              void* d_out, int out_size) {
    const float* x  = (const float*)d_in[0];
    const float* W1 = (const float*)d_in[1];
    const float* b1 = (const float*)d_in[2];
    const float* W2 = (const float*)d_in[3];
    const float* b2 = (const float*)d_in[4];
    float* out = (float*)d_out;

    prep_kernel<<<NBR, HID>>>(W1, b1);
    build_kernel<<<dim3(EMB / DCH, NBR), DCH>>>(W2, b2);
    apply_kernel<<<dim3(BATCH / BCH, NBR), ATHREADS>>>(x, out);
}

// round 5
// speedup vs baseline: 1.6335x; 1.6335x over previous
#include <cuda_runtime.h>
#include <cstdint>
#include <cstddef>

// ============================================================================
// Problem dims
// ============================================================================
constexpr int NBR = 36;    // branches (IN_DIM)
constexpr int HID = 512;
constexpr int EMB = 1024;
constexpr int NSEG = HID + 1;  // 513 table rows per branch
constexpr int BATCH = 2048;

constexpr int SEGS = 8;            // rank segments
constexpr int RSEG = HID / SEGS;   // 64 ranks per segment
constexpr int DTH  = 256;          // threads per build block
constexpr int DCHUNKS = EMB / DTH; // 4 d-chunks

// ============================================================================
// Scratch (__device__ globals — no runtime allocation)
// ============================================================================
__device__ float g_tsort[NBR * HID];   // sorted knees per branch
__device__ int   g_sidx [NBR * HID];   // original unit index, sorted order
__device__ float g_dss  [NBR * HID];   // slope delta, sorted order
__device__ float g_dcs  [NBR * HID];   // intercept delta, sorted order
__device__ float g_slos [NBR * HID];   // base slope, sorted order
__device__ float g_clos [NBR * HID];   // base intercept, sorted order

// Segment partial sums: [NBR][SEGS][EMB]
__device__ float g_Bsl[NBR * SEGS * EMB];
__device__ float g_Bsc[NBR * SEGS * EMB];
__device__ float g_Pds[NBR * SEGS * EMB];
__device__ float g_Pdc[NBR * SEGS * EMB];

// Fused table: per (branch, rank) one row of 2*EMB floats: [SL | SC]
__device__ float g_T[(size_t)NBR * NSEG * 2 * EMB];  // 151 MB

// ============================================================================
// Kernel 1: knees + bitonic sort (36 blocks x 512 thr)
//
// leaky(z) = z (z>=0) else 0.01 z,  z = W1*x + b1;  knee t = -b1/W1.
//  W1>0: x<t -> (0.01W1,0.01b1); x>=t -> (W1,b1)       => ds=+0.99W1, dc=+0.99b1
//  W1<0: x<t -> (W1,b1);         x>=t -> (0.01W1,0.01b1) => ds=-0.99W1, dc=-0.99b1
//  W1=0: constant; t=+inf, ds=dc=0
// (out is continuous at each knee, so rank ties are harmless.)
// ============================================================================
__global__ void __launch_bounds__(HID)
prep_kernel(const float* __restrict__ W1, const float* __restrict__ b1) {
    __shared__ float sk[HID];
    __shared__ int   sv[HID];
    __shared__ float sds[HID];
    __shared__ float sdc[HID];
    __shared__ float sslo[HID];
    __shared__ float sclo[HID];

    const int i = blockIdx.x;
    const int j = threadIdx.x;

    const float w = W1[i * HID + j];
    const float b = b1[i * HID + j];

    float t, slo, clo, ds, dc;
    if (w > 0.0f) {
        t = -b / w;
        slo = 0.01f * w; clo = 0.01f * b;
        ds = 0.99f * w;  dc = 0.99f * b;
    } else if (w < 0.0f) {
        t = -b / w;
        slo = w; clo = b;
        ds = -0.99f * w; dc = -0.99f * b;
    } else {
        t = __int_as_float(0x7f800000);  // +inf (never crossed)
        slo = 0.0f;
        clo = (b >= 0.0f) ? b : 0.01f * b;
        ds = 0.0f; dc = 0.0f;
    }

    sk[j] = t; sv[j] = j;
    sds[j] = ds; sdc[j] = dc;
    sslo[j] = slo; sclo[j] = clo;
    __syncthreads();

    // Bitonic sort ascending on sk, carrying sv
    for (int k = 2; k <= HID; k <<= 1) {
        for (int jj = k >> 1; jj > 0; jj >>= 1) {
            int ixj = j ^ jj;
            if (ixj > j) {
                bool up = ((j & k) == 0);
                float a = sk[j], c = sk[ixj];
                bool sw = up ? (a > c) : (a < c);
                if (sw) {
                    sk[j] = c; sk[ixj] = a;
                    int tv = sv[j]; sv[j] = sv[ixj]; sv[ixj] = tv;
                }
            }
            __syncthreads();
        }
    }

    const int src = sv[j];
    g_tsort[i * HID + j] = sk[j];
    g_sidx [i * HID + j] = src;
    g_dss  [i * HID + j] = sds[src];
    g_dcs  [i * HID + j] = sdc[src];
    g_slos [i * HID + j] = sslo[src];
    g_clos [i * HID + j] = sclo[src];
}

// ============================================================================
// Kernel 2a: segment partial sums. grid (DCHUNKS, SEGS, NBR), DTH threads.
//   Bsl[i,s,d] = sum_{r in seg} slo_r * W2[i, ix_r, d]   (base partials)
//   Bsc[i,s,d] = sum_{r in seg} clo_r * W2[i, ix_r, d]
//   Pds[i,s,d] = sum_{r in seg} ds_r  * W2[i, ix_r, d]   (delta partials)
//   Pdc[i,s,d] = sum_{r in seg} dc_r  * W2[i, ix_r, d]
// 2304 blocks, 62 warps/SM -> W2 read at BW, chains only 64 deep.
// ============================================================================
__global__ void __launch_bounds__(DTH)
partial_kernel(const float* __restrict__ W2) {
    __shared__ int   six[RSEG];
    __shared__ float ssl[RSEG], scl[RSEG], sds[RSEG], sdc[RSEG];

    const int i = blockIdx.z;
    const int s = blockIdx.y;
    const int d = blockIdx.x * DTH + threadIdx.x;
    const int tid = threadIdx.x;

    if (tid < RSEG) {
        int r = s * RSEG + tid;
        six[tid] = g_sidx[i * HID + r];
        ssl[tid] = g_slos[i * HID + r];
        scl[tid] = g_clos[i * HID + r];
        sds[tid] = g_dss [i * HID + r];
        sdc[tid] = g_dcs [i * HID + r];
    }
    __syncthreads();

    const float* w2 = W2 + (size_t)i * HID * EMB + d;

    float bsl = 0.0f, bsc = 0.0f, pds = 0.0f, pdc = 0.0f;
#pragma unroll 8
    for (int k = 0; k < RSEG; k++) {
        float wv = __ldg(w2 + (size_t)six[k] * EMB);
        bsl = fmaf(ssl[k], wv, bsl);
        bsc = fmaf(scl[k], wv, bsc);
        pds = fmaf(sds[k], wv, pds);
        pdc = fmaf(sdc[k], wv, pdc);
    }

    const int o = (i * SEGS + s) * EMB + d;
    g_Bsl[o] = bsl;
    g_Bsc[o] = bsc;
    g_Pds[o] = pds;
    g_Pdc[o] = pdc;
}

// ============================================================================
// Kernel 2b: scan + table write. grid (DCHUNKS, SEGS, NBR), DTH threads.
//   start(s) = b2 + sum_all Bs + sum_{s'<s} P;  then 64-step serial prefix.
//   Segment s writes rows [s*64, (s+1)*64); last segment also writes row 512.
//   W2 re-read hits L2 (touched by K2a just before). Partials are L2-hot.
// ============================================================================
__global__ void __launch_bounds__(DTH)
scan_kernel(const float* __restrict__ W2, const float* __restrict__ b2) {
    __shared__ int   six[RSEG];
    __shared__ float sds[RSEG], sdc[RSEG];

    const int i = blockIdx.z;
    const int s = blockIdx.y;
    const int d = blockIdx.x * DTH + threadIdx.x;
    const int tid = threadIdx.x;

    if (tid < RSEG) {
        int r = s * RSEG + tid;
        six[tid] = g_sidx[i * HID + r];
        sds[tid] = g_dss [i * HID + r];
        sdc[tid] = g_dcs [i * HID + r];
    }
    __syncthreads();

    // Start offsets: base (all segments' B partials) + deltas of segments < s
    float sl = 0.0f;
    float sc = b2[i * EMB + d];
#pragma unroll
    for (int s2 = 0; s2 < SEGS; s2++) {
        int o = (i * SEGS + s2) * EMB + d;
        sl += __ldg(g_Bsl + o);
        sc += __ldg(g_Bsc + o);
    }
#pragma unroll
    for (int s2 = 0; s2 < SEGS - 1; s2++) {
        if (s2 < s) {
            int o = (i * SEGS + s2) * EMB + d;
            sl += __ldg(g_Pds + o);
            sc += __ldg(g_Pdc + o);
        }
    }

    const float* w2 = W2 + (size_t)i * HID * EMB + d;
    float* trow = g_T + ((size_t)i * NSEG + s * RSEG) * (2 * EMB) + d;

    // Row s*RSEG = segment start
    trow[0]   = sl;
    trow[EMB] = sc;

    const bool last = (s == SEGS - 1);
#pragma unroll 8
    for (int k = 0; k < RSEG; k++) {
        float wv = __ldg(w2 + (size_t)six[k] * EMB);
        sl = fmaf(sds[k], wv, sl);
        sc = fmaf(sdc[k], wv, sc);
        if (k < RSEG - 1 || last) {
            trow[(size_t)(k + 1) * (2 * EMB)]       = sl;
            trow[(size_t)(k + 1) * (2 * EMB) + EMB] = sc;
        }
    }
}

// ============================================================================
// Kernel 3: apply. grid (BATCH/BCH, NBR), 256 threads.
//   out[b,i,d] = x[b,i] * SL[i, r(x), d] + SC[i, r(x), d]
// blockIdx.x fastest -> one branch's 64 blocks run ~together; the branch's
// 4.2 MB table slice stays L2-resident across them.
// ============================================================================
constexpr int BCH = 32;
constexpr int ATHREADS = 256;  // 256 * float4 = 1024 d

__global__ void __launch_bounds__(ATHREADS)
apply_kernel(const float* __restrict__ x, float* __restrict__ out) {
    __shared__ float s_t[HID];
    __shared__ float s_x[BCH];
    __shared__ int   s_r[BCH];

    const int i = blockIdx.y;
    const int b0 = blockIdx.x * BCH;
    const int tid = threadIdx.x;

    for (int r = tid; r < HID; r += ATHREADS)
        s_t[r] = g_tsort[i * HID + r];
    __syncthreads();

    if (tid < BCH) {
        const float xv = x[(size_t)(b0 + tid) * NBR + i];
        // r = count of knees <= xv (9-step binary search)
        int lo = 0, hi = HID;
        while (lo < hi) {
            int mid = (lo + hi) >> 1;
            if (s_t[mid] <= xv) lo = mid + 1; else hi = mid;
        }
        s_x[tid] = xv;
        s_r[tid] = lo;
    }
    __syncthreads();

    const int d4 = tid * 4;
#pragma unroll 2
    for (int bb = 0; bb < BCH; bb++) {
        const int r = s_r[bb];
        const float xv = s_x[bb];
        const float* trow = g_T + ((size_t)i * NSEG + r) * (2 * EMB);
        float4 sl = *(const float4*)(trow + d4);
        float4 sc = *(const float4*)(trow + EMB + d4);
        float4 v;
        v.x = fmaf(xv, sl.x, sc.x);
        v.y = fmaf(xv, sl.y, sc.y);
        v.z = fmaf(xv, sl.z, sc.z);
        v.w = fmaf(xv, sl.w, sc.w);
        *(float4*)(out + ((size_t)(b0 + bb) * NBR + i) * EMB + d4) = v;
    }
}

// ============================================================================
// Launch
// ============================================================================
extern "C" void kernel_launch(void* const* d_in, const int* in_sizes, int n_in,
                              void* d_out, int out_size) {
    const float* x  = (const float*)d_in[0];
    const float* W1 = (const float*)d_in[1];
    const float* b1 = (const float*)d_in[2];
    const float* W2 = (const float*)d_in[3];
    const float* b2 = (const float*)d_in[4];
    float* out = (float*)d_out;

    prep_kernel<<<NBR, HID>>>(W1, b1);
    partial_kernel<<<dim3(DCHUNKS, SEGS, NBR), DTH>>>(W2);
    scan_kernel<<<dim3(DCHUNKS, SEGS, NBR), DTH>>>(W2, b2);
    apply_kernel<<<dim3(BATCH / BCH, NBR), ATHREADS>>>(x, out);
}

// round 7
// speedup vs baseline: 1.6938x; 1.0369x over previous
#include <cuda_runtime.h>
#include <cstdint>
#include <cstddef>

// ============================================================================
// Problem dims
// ============================================================================
constexpr int NBR = 36;    // branches (IN_DIM)
constexpr int HID = 512;
constexpr int EMB = 1024;
constexpr int NSEG = HID + 1;  // 513 table rows per branch
constexpr int BATCH = 2048;

constexpr int SEGS = 8;            // rank segments
constexpr int RSEG = HID / SEGS;   // 64 ranks per segment
constexpr int DTH  = 256;          // threads per build block
constexpr int DCHUNKS = EMB / DTH; // 4 d-chunks
constexpr int NFLAGS = NBR * DCHUNKS * SEGS;  // 1152

// ============================================================================
// Scratch (__device__ globals — no runtime allocation)
// ============================================================================
__device__ float g_tsort[NBR * HID];   // sorted knees per branch
__device__ int   g_sidx [NBR * HID];   // original unit index, sorted order
__device__ float g_dss  [NBR * HID];   // slope delta, sorted order
__device__ float g_dcs  [NBR * HID];   // intercept delta, sorted order
__device__ float g_slos [NBR * HID];   // base slope, sorted order
__device__ float g_clos [NBR * HID];   // base intercept, sorted order

// Segment partial sums: [NBR][SEGS][EMB]
__device__ float g_Bsl[NBR * SEGS * EMB];
__device__ float g_Bsc[NBR * SEGS * EMB];
__device__ float g_Pds[NBR * SEGS * EMB];
__device__ float g_Pdc[NBR * SEGS * EMB];

// Lookback flags, one per (branch, d-chunk, segment). Zeroed by prep_kernel.
__device__ int g_flag[NFLAGS];

// Fused table: per (branch, rank) one row of 2*EMB floats: [SL | SC]
__device__ float g_T[(size_t)NBR * NSEG * 2 * EMB];  // 151 MB

// ============================================================================
// Kernel 1: knees + bitonic sort (36 blocks x 512 thr) + flag zeroing
//
// leaky(z) = z (z>=0) else 0.01 z,  z = W1*x + b1;  knee t = -b1/W1.
//  W1>0: x<t -> (0.01W1,0.01b1); x>=t -> (W1,b1)       => ds=+0.99W1, dc=+0.99b1
//  W1<0: x<t -> (W1,b1);         x>=t -> (0.01W1,0.01b1) => ds=-0.99W1, dc=-0.99b1
//  W1=0: constant; t=+inf, ds=dc=0
// (out is continuous at each knee, so rank ties are harmless.)
// ============================================================================
__global__ void __launch_bounds__(HID)
prep_kernel(const float* __restrict__ W1, const float* __restrict__ b1) {
    __shared__ float sk[HID];
    __shared__ int   sv[HID];
    __shared__ float sds[HID];
    __shared__ float sdc[HID];
    __shared__ float sslo[HID];
    __shared__ float sclo[HID];

    const int i = blockIdx.x;
    const int j = threadIdx.x;

    // Zero lookback flags for the fused build kernel (runs after us in-stream)
    {
        int g = i * HID + j;
        if (g < NFLAGS) g_flag[g] = 0;
    }

    const float w = W1[i * HID + j];
    const float b = b1[i * HID + j];

    float t, slo, clo, ds, dc;
    if (w > 0.0f) {
        t = -b / w;
        slo = 0.01f * w; clo = 0.01f * b;
        ds = 0.99f * w;  dc = 0.99f * b;
    } else if (w < 0.0f) {
        t = -b / w;
        slo = w; clo = b;
        ds = -0.99f * w; dc = -0.99f * b;
    } else {
        t = __int_as_float(0x7f800000);  // +inf (never crossed)
        slo = 0.0f;
        clo = (b >= 0.0f) ? b : 0.01f * b;
        ds = 0.0f; dc = 0.0f;
    }

    sk[j] = t; sv[j] = j;
    sds[j] = ds; sdc[j] = dc;
    sslo[j] = slo; sclo[j] = clo;
    __syncthreads();

    // Bitonic sort ascending on sk, carrying sv
    for (int k = 2; k <= HID; k <<= 1) {
        for (int jj = k >> 1; jj > 0; jj >>= 1) {
            int ixj = j ^ jj;
            if (ixj > j) {
                bool up = ((j & k) == 0);
                float a = sk[j], c = sk[ixj];
                bool sw = up ? (a > c) : (a < c);
                if (sw) {
                    sk[j] = c; sk[ixj] = a;
                    int tv = sv[j]; sv[j] = sv[ixj]; sv[ixj] = tv;
                }
            }
            __syncthreads();
        }
    }

    const int src = sv[j];
    g_tsort[i * HID + j] = sk[j];
    g_sidx [i * HID + j] = src;
    g_dss  [i * HID + j] = sds[src];
    g_dcs  [i * HID + j] = sdc[src];
    g_slos [i * HID + j] = sslo[src];
    g_clos [i * HID + j] = sclo[src];
}

// ============================================================================
// Kernel 2 (fused): partials + lookback + prefix, reading W2 ONCE.
// grid (DCHUNKS, SEGS, NBR), DTH threads.
//   Phase 1: gather this segment's 64 W2 columns (d-chunk) into registers,
//            compute 4 partial sums, publish (fence + flag).
//   Phase 2: wait for all 8 segment flags of this (branch, d-chunk) group,
//            base = b2 + sum_all Bsl/Bsc; start += deltas of segments < s
//            (fixed summation order -> deterministic),
//            then 64-step serial prefix from registers, write 64 table rows.
//   Segment s writes rows [s*64, (s+1)*64); last segment also writes row 512.
// Progress: group members span <= 28 bids; ~296 blocks resident -> no deadlock.
// ============================================================================
__global__ void __launch_bounds__(DTH, 2)
build_fused_kernel(const float* __restrict__ W2, const float* __restrict__ b2) {
    __shared__ int   six[RSEG];
    __shared__ float ssl[RSEG], scl[RSEG], sds[RSEG], sdc[RSEG];

    const int i = blockIdx.z;
    const int s = blockIdx.y;
    const int xc = blockIdx.x;
    const int d = xc * DTH + threadIdx.x;
    const int tid = threadIdx.x;

    if (tid < RSEG) {
        int r = s * RSEG + tid;
        six[tid] = g_sidx[i * HID + r];
        ssl[tid] = g_slos[i * HID + r];
        scl[tid] = g_clos[i * HID + r];
        sds[tid] = g_dss [i * HID + r];
        sdc[tid] = g_dcs [i * HID + r];
    }
    __syncthreads();

    // ---- Phase 1: gather W2 columns into registers + partials ----
    const float* w2 = W2 + (size_t)i * HID * EMB + d;
    float v[RSEG];
#pragma unroll
    for (int k = 0; k < RSEG; k++)
        v[k] = __ldg(w2 + (size_t)six[k] * EMB);

    float bsl = 0.0f, bsc = 0.0f, pds = 0.0f, pdc = 0.0f;
#pragma unroll
    for (int k = 0; k < RSEG; k++) {
        bsl = fmaf(ssl[k], v[k], bsl);
        bsc = fmaf(scl[k], v[k], bsc);
        pds = fmaf(sds[k], v[k], pds);
        pdc = fmaf(sdc[k], v[k], pdc);
    }

    const int o = (i * SEGS + s) * EMB + d;
    g_Bsl[o] = bsl;
    g_Bsc[o] = bsc;
    g_Pds[o] = pds;
    g_Pdc[o] = pdc;

    // Publish: all threads fence their stores, then tid 0 raises the flag.
    __threadfence();
    __syncthreads();
    const int fbase = (i * DCHUNKS + xc) * SEGS;
    if (tid == 0)
        ((volatile int*)g_flag)[fbase + s] = 1;

    // ---- Wait for all 8 segment flags of this group ----
    if (tid < SEGS) {
        volatile int* f = (volatile int*)g_flag + fbase + tid;
        while (*f == 0) { __nanosleep(60); }
    }
    __threadfence();
    __syncthreads();

    // ---- Phase 2: start offsets (fixed order -> deterministic) ----
    float sl = 0.0f;
    float sc = __ldg(b2 + i * EMB + d);
#pragma unroll
    for (int s2 = 0; s2 < SEGS; s2++) {
        int oo = (i * SEGS + s2) * EMB + d;
        sl += __ldcg(g_Bsl + oo);
        sc += __ldcg(g_Bsc + oo);
    }
#pragma unroll
    for (int s2 = 0; s2 < SEGS - 1; s2++) {
        if (s2 < s) {
            int oo = (i * SEGS + s2) * EMB + d;
            sl += __ldcg(g_Pds + oo);
            sc += __ldcg(g_Pdc + oo);
        }
    }

    // ---- Serial prefix from registers; write table rows ----
    float* trow = g_T + ((size_t)i * NSEG + s * RSEG) * (2 * EMB) + d;
    trow[0]   = sl;   // row s*RSEG (segment start)
    trow[EMB] = sc;

    const bool last = (s == SEGS - 1);
#pragma unroll
    for (int k = 0; k < RSEG; k++) {
        sl = fmaf(sds[k], v[k], sl);
        sc = fmaf(sdc[k], v[k], sc);
        if (k < RSEG - 1 || last) {
            trow[(size_t)(k + 1) * (2 * EMB)]       = sl;
            trow[(size_t)(k + 1) * (2 * EMB) + EMB] = sc;
        }
    }
}

// ============================================================================
// Kernel 3: apply. grid (BATCH/BCH, NBR), 256 threads.
//   out[b,i,d] = x[b,i] * SL[i, r(x), d] + SC[i, r(x), d]
// blockIdx.x fastest -> one branch's 64 blocks run ~together; the branch's
// 4.2 MB table slice stays L2-resident. Out is written with __stcs so the
// write-once stream doesn't evict the hot table from L2.
// ============================================================================
constexpr int BCH = 32;
constexpr int ATHREADS = 256;  // 256 * float4 = 1024 d

__global__ void __launch_bounds__(ATHREADS)
apply_kernel(const float* __restrict__ x, float* __restrict__ out) {
    __shared__ float s_t[HID];
    __shared__ float s_x[BCH];
    __shared__ int   s_r[BCH];

    const int i = blockIdx.y;
    const int b0 = blockIdx.x * BCH;
    const int tid = threadIdx.x;

    for (int r = tid; r < HID; r += ATHREADS)
        s_t[r] = g_tsort[i * HID + r];
    __syncthreads();

    if (tid < BCH) {
        const float xv = x[(size_t)(b0 + tid) * NBR + i];
        // r = count of knees <= xv (9-step binary search)
        int lo = 0, hi = HID;
        while (lo < hi) {
            int mid = (lo + hi) >> 1;
            if (s_t[mid] <= xv) lo = mid + 1; else hi = mid;
        }
        s_x[tid] = xv;
        s_r[tid] = lo;
    }
    __syncthreads();

    const int d4 = tid * 4;
#pragma unroll 4
    for (int bb = 0; bb < BCH; bb++) {
        const int r = s_r[bb];
        const float xv = s_x[bb];
        const float* trow = g_T + ((size_t)i * NSEG + r) * (2 * EMB);
        float4 sl = *(const float4*)(trow + d4);
        float4 sc = *(const float4*)(trow + EMB + d4);
        float4 v;
        v.x = fmaf(xv, sl.x, sc.x);
        v.y = fmaf(xv, sl.y, sc.y);
        v.z = fmaf(xv, sl.z, sc.z);
        v.w = fmaf(xv, sl.w, sc.w);
        __stcs((float4*)(out + ((size_t)(b0 + bb) * NBR + i) * EMB + d4), v);
    }
}

// ============================================================================
// Launch
// ============================================================================
extern "C" void kernel_launch(void* const* d_in, const int* in_sizes, int n_in,
                              void* d_out, int out_size) {
    const float* x  = (const float*)d_in[0];
    const float* W1 = (const float*)d_in[1];
    const float* b1 = (const float*)d_in[2];
    const float* W2 = (const float*)d_in[3];
    const float* b2 = (const float*)d_in[4];
    float* out = (float*)d_out;

    prep_kernel<<<NBR, HID>>>(W1, b1);
    build_fused_kernel<<<dim3(DCHUNKS, SEGS, NBR), DTH>>>(W2, b2);
    apply_kernel<<<dim3(BATCH / BCH, NBR), ATHREADS>>>(x, out);
}